// round 5
// baseline (speedup 1.0000x reference)
#include <cuda_runtime.h>
#include <cuda_bf16.h>
#include <cstdint>
#include <math.h>

// ---------------- problem constants ----------------
#define D      2560
#define SSELF  2048
#define SCROSS 512
#define NB     2
#define NH     20
#define HDIM   128
#define FFND   10240
#define TOK    4096
#define TOKC   1024
#define BH     40
#define EPSV   1e-6f

typedef __nv_bfloat16 bf16;

// ---------------- scratch (device globals) ----------------
__device__ float g_qkv [(size_t)TOK * 3 * D];
__device__ float g_kv2 [(size_t)TOKC * 2 * D];
__device__ float g_h1  [(size_t)TOK * D];
__device__ float g_h2  [(size_t)TOK * D];
__device__ float g_attn[(size_t)TOK * D];
__device__ float g_mid [(size_t)TOK * FFND];
__device__ float g_logits[(size_t)BH * SSELF * SSELF];

// attention bf16 split buffers
__device__ bf16 g_qh[(size_t)TOK * D],  g_ql[(size_t)TOK * D];
__device__ bf16 g_kh[(size_t)TOK * D],  g_kl[(size_t)TOK * D];
__device__ bf16 g_vh[(size_t)TOK * D],  g_vl[(size_t)TOK * D];
__device__ bf16 g_Ph[(size_t)BH * SSELF * SSELF], g_Pl[(size_t)BH * SSELF * SSELF];

// int8 activation buffers (shared, reused sequentially)
__device__ int8_t g_a8h[(size_t)TOK * FFND], g_a8l[(size_t)TOK * FFND];
__device__ float  g_sact[TOK];
__device__ int8_t g_e8h[(size_t)TOKC * D], g_e8l[(size_t)TOKC * D];
__device__ float  g_se[TOKC];

// int8 weights + scales
__device__ int8_t g_wqkv8h[(size_t)3 * D * D], g_wqkv8l[(size_t)3 * D * D];
__device__ float  g_swqkv[3 * D];
__device__ int8_t g_wo18h [(size_t)D * D],     g_wo18l [(size_t)D * D];
__device__ float  g_swo1[D];
__device__ int8_t g_wq28h [(size_t)D * D],     g_wq28l [(size_t)D * D];
__device__ float  g_swq2[D];
__device__ int8_t g_wkv28h[(size_t)2 * D * D], g_wkv28l[(size_t)2 * D * D];
__device__ float  g_swkv2[2 * D];
__device__ int8_t g_wo28h [(size_t)D * D],     g_wo28l [(size_t)D * D];
__device__ float  g_swo2[D];
__device__ int8_t g_wff18h[(size_t)FFND * D],  g_wff18l[(size_t)FFND * D];
__device__ float  g_swff1[FFND];
__device__ int8_t g_wff28h[(size_t)D * FFND],  g_wff28l[(size_t)D * FFND];
__device__ float  g_swff2[D];

// ---------------- small helpers ----------------
__device__ __forceinline__ void split2(float v, bf16& h, bf16& l) {
    h = __float2bfloat16(v);
    l = __float2bfloat16(v - __bfloat162float(h));
}

__device__ __forceinline__ float fast_gelu(float x) {
    float u = 0.7978845608028654f * (x + 0.044715f * x * x * x);
    float t = 1.0f - 2.0f / (1.0f + __expf(2.0f * u));
    return 0.5f * x * (1.0f + t);
}

__device__ __forceinline__ void quant_pair(float u, int8_t& hi, int8_t& lo) {
    float h = rintf(u);
    h = fminf(fmaxf(h, -127.f), 127.f);
    float l = rintf((u - h) * 252.f);
    hi = (int8_t)(int)h;
    lo = (int8_t)(int)l;
}

__device__ __forceinline__ uint32_t smem_u32(const void* p) {
    uint32_t a;
    asm("{ .reg .u64 t; cvta.to.shared.u64 t, %1; cvt.u32.u64 %0, t; }" : "=r"(a) : "l"(p));
    return a;
}

#define CP_ASYNC16(dst, src) \
    asm volatile("cp.async.cg.shared.global [%0], [%1], 16;" :: "r"(dst), "l"(src))
#define CP_COMMIT() asm volatile("cp.async.commit_group;" ::: "memory")
#define CP_WAIT1()  asm volatile("cp.async.wait_group 1;" ::: "memory")

__device__ __forceinline__ void ldsm4(uint32_t* r, uint32_t addr) {
    asm volatile("ldmatrix.sync.aligned.m8n8.x4.shared.b16 {%0,%1,%2,%3}, [%4];"
        : "=r"(r[0]), "=r"(r[1]), "=r"(r[2]), "=r"(r[3]) : "r"(addr));
}

__device__ __forceinline__ void mma16816(float* c, const uint32_t* a, const uint32_t* b) {
    asm volatile("mma.sync.aligned.m16n8k16.row.col.f32.bf16.bf16.f32 "
        "{%0,%1,%2,%3}, {%4,%5,%6,%7}, {%8,%9}, {%0,%1,%2,%3};"
        : "+f"(c[0]), "+f"(c[1]), "+f"(c[2]), "+f"(c[3])
        : "r"(a[0]), "r"(a[1]), "r"(a[2]), "r"(a[3]), "r"(b[0]), "r"(b[1]));
}

__device__ __forceinline__ void mma16832i8(int* c, const uint32_t* a, const uint32_t* b) {
    asm volatile("mma.sync.aligned.m16n8k32.row.col.s32.s8.s8.s32 "
        "{%0,%1,%2,%3}, {%4,%5,%6,%7}, {%8,%9}, {%0,%1,%2,%3};"
        : "+r"(c[0]), "+r"(c[1]), "+r"(c[2]), "+r"(c[3])
        : "r"(a[0]), "r"(a[1]), "r"(a[2]), "r"(a[3]), "r"(b[0]), "r"(b[1]));
}

// ---------------- reductions ----------------
__device__ __forceinline__ float blockReduceSum(float v) {
    __shared__ float sh[32];
    int lane = threadIdx.x & 31, wid = threadIdx.x >> 5;
    #pragma unroll
    for (int o = 16; o > 0; o >>= 1) v += __shfl_xor_sync(0xffffffffu, v, o);
    __syncthreads();
    if (lane == 0) sh[wid] = v;
    __syncthreads();
    int nw = blockDim.x >> 5;
    float r = (threadIdx.x < nw) ? sh[threadIdx.x] : 0.0f;
    if (wid == 0) {
        #pragma unroll
        for (int o = 16; o > 0; o >>= 1) r += __shfl_xor_sync(0xffffffffu, r, o);
        if (lane == 0) sh[0] = r;
    }
    __syncthreads();
    return sh[0];
}

__device__ __forceinline__ float blockReduceMax(float v) {
    __shared__ float sh[32];
    int lane = threadIdx.x & 31, wid = threadIdx.x >> 5;
    #pragma unroll
    for (int o = 16; o > 0; o >>= 1) v = fmaxf(v, __shfl_xor_sync(0xffffffffu, v, o));
    __syncthreads();
    if (lane == 0) sh[wid] = v;
    __syncthreads();
    int nw = blockDim.x >> 5;
    float r = (threadIdx.x < nw) ? sh[threadIdx.x] : -3.4e38f;
    if (wid == 0) {
        #pragma unroll
        for (int o = 16; o > 0; o >>= 1) r = fmaxf(r, __shfl_xor_sync(0xffffffffu, r, o));
        if (lane == 0) sh[0] = r;
    }
    __syncthreads();
    return sh[0];
}

// ---------------- LN -> int8 hi/lo + row scale ----------------
__global__ void __launch_bounds__(256) ln_q8_kernel(
    const float* __restrict__ in,
    int8_t* __restrict__ oh, int8_t* __restrict__ ol, float* __restrict__ sc,
    const float* __restrict__ gamma, const float* __restrict__ beta,
    const float* __restrict__ sst, const float* __restrict__ temb,
    int iShift, int iScale, int rowsPerB)
{
    long long r = blockIdx.x;
    const float* x = in + r * D;
    float s1 = 0.f, s2 = 0.f;
    #pragma unroll
    for (int i = 0; i < D / 256; i++) {
        float v = x[threadIdx.x + i * 256];
        s1 += v; s2 += v * v;
    }
    s1 = blockReduceSum(s1);
    s2 = blockReduceSum(s2);
    float mean = s1 * (1.0f / D);
    float var  = s2 * (1.0f / D) - mean * mean;
    float rstd = rsqrtf(var + EPSV);
    int b = (int)(r / rowsPerB);
    float yv[D / 256];
    float mx = 0.f;
    #pragma unroll
    for (int i = 0; i < D / 256; i++) {
        int d = threadIdx.x + i * 256;
        float y = (x[d] - mean) * rstd;
        if (sst) {
            float scm = sst[iScale * D + d] + temb[((long long)b * 6 + iScale) * D + d];
            float shm = sst[iShift * D + d] + temb[((long long)b * 6 + iShift) * D + d];
            y = y * (1.f + scm) + shm;
        } else if (gamma) {
            y = y * gamma[d] + beta[d];
        }
        yv[i] = y;
        mx = fmaxf(mx, fabsf(y));
    }
    mx = blockReduceMax(mx);
    float sa  = mx * (1.0f / 127.0f);
    float inv = (mx > 0.f) ? 127.0f / mx : 0.f;
    if (threadIdx.x == 0) sc[r] = sa;
    #pragma unroll
    for (int i = 0; i < D / 256; i++) {
        int d = threadIdx.x + i * 256;
        int8_t hi, lo; quant_pair(yv[i] * inv, hi, lo);
        oh[r * D + d] = hi; ol[r * D + d] = lo;
    }
}

// ---------------- generic rowwise fp32 -> int8 hi/lo quant (two-pass) ----------------
__global__ void __launch_bounds__(256) quant8_kernel(
    const float* __restrict__ in, int cols,
    int8_t* __restrict__ oh, int8_t* __restrict__ ol, float* __restrict__ sc)
{
    long long r = blockIdx.x;
    const float* x = in + r * (long long)cols;
    float mx = 0.f;
    for (int d = threadIdx.x; d < cols; d += 256) mx = fmaxf(mx, fabsf(x[d]));
    mx = blockReduceMax(mx);
    float sa  = mx * (1.0f / 127.0f);
    float inv = (mx > 0.f) ? 127.0f / mx : 0.f;
    if (threadIdx.x == 0) sc[r] = sa;
    for (int d = threadIdx.x; d < cols; d += 256) {
        int8_t hi, lo; quant_pair(x[d] * inv, hi, lo);
        oh[r * (long long)cols + d] = hi; ol[r * (long long)cols + d] = lo;
    }
}

// ---------------- attention producers (bf16 hi/lo) ----------------
__global__ void __launch_bounds__(256) rms_heads_kernel(
    const float* __restrict__ in, int ldin, int off,
    const float* __restrict__ w, bf16* __restrict__ oh, bf16* __restrict__ ol, int Srows,
    const float* __restrict__ rcos, const float* __restrict__ rsin)
{
    long long r = blockIdx.x;
    int b = (int)(r / Srows), s = (int)(r % Srows);
    const float* x = in + r * ldin + off;
    float s2 = 0.f;
    for (int d = threadIdx.x; d < D; d += 256) { float v = x[d]; s2 += v * v; }
    s2 = blockReduceSum(s2);
    float rms = rsqrtf(s2 * (1.0f / D) + EPSV);
    for (int d = threadIdx.x; d < D; d += 256) {
        int h = d >> 7, dd = d & 127;
        float v = x[d] * rms * w[d];
        if (rcos) {
            int pd = (dd < 64) ? d + 64 : d - 64;
            float vp = x[pd] * rms * w[pd];
            float c = rcos[s * HDIM + dd], sn = rsin[s * HDIM + dd];
            v = (dd < 64) ? (v * c - vp * sn) : (v * c + vp * sn);
        }
        long long oi = (((long long)(b * NH + h)) * Srows + s) * HDIM + dd;
        bf16 hh, ll; split2(v, hh, ll);
        oh[oi] = hh; ol[oi] = ll;
    }
}

__global__ void __launch_bounds__(256) vtrans_kernel(
    const float* __restrict__ in, int ldin, int off,
    bf16* __restrict__ oh, bf16* __restrict__ ol, int Srows, long long total)
{
    for (long long i = blockIdx.x * 256LL + threadIdx.x; i < total; i += (long long)gridDim.x * 256) {
        long long r = i / D; int col = (int)(i % D);
        int h = col >> 7, d = col & 127;
        int b = (int)(r / Srows), s = (int)(r % Srows);
        long long oi = (((long long)(b * NH + h)) * HDIM + d) * Srows + s;
        bf16 hh, ll; split2(in[r * ldin + off + col], hh, ll);
        oh[oi] = hh; ol[oi] = ll;
    }
}

__global__ void __launch_bounds__(256) softmax_kernel(
    float* __restrict__ p, bf16* __restrict__ oh, bf16* __restrict__ ol, int len)
{
    long long r = blockIdx.x;
    float* x = p + r * (long long)len;
    float mx = -3.4e38f;
    for (int d = threadIdx.x; d < len; d += 256) mx = fmaxf(mx, x[d]);
    mx = blockReduceMax(mx);
    float sum = 0.f;
    for (int d = threadIdx.x; d < len; d += 256) { float e = __expf(x[d] - mx); x[d] = e; sum += e; }
    sum = blockReduceSum(sum);
    float inv = 1.0f / sum;
    for (int d = threadIdx.x; d < len; d += 256) {
        float v = x[d] * inv;
        bf16 hh, ll; split2(v, hh, ll);
        oh[r * (long long)len + d] = hh; ol[r * (long long)len + d] = ll;
    }
}

// ================= shared GEMM tile config =================
// stage layout: 4 sub-tiles of 8KB each (A-hi, A-lo, B-hi, B-lo), rows of 64 bytes
#define STAGE_BYTES 32768
#define OFF_AH 0
#define OFF_AL 8192
#define OFF_BH 16384
#define OFF_BL 24576
#define NSTAGE 3
#define GEMM_SMEM (NSTAGE * STAGE_BYTES)

__device__ __forceinline__ uint32_t tswz(int row, int chunk) {
    return (uint32_t)(row * 64 + ((chunk ^ (row & 3)) << 4));
}

// ---------------- bf16 split GEMM (attention only) ----------------
// BK = 32 bf16 (64 bytes)
__global__ void __launch_bounds__(256, 1) gemm_bf16_kernel(
    const bf16* __restrict__ Ah, const bf16* __restrict__ Al,
    const bf16* __restrict__ Bh, const bf16* __restrict__ Bl,
    float* __restrict__ C,
    int K, int lda, int ldb, int ldc,
    long long sAo, long long sAi, long long sBo, long long sBi,
    long long sCo, long long sCi, int innerN, float alpha)
{
    extern __shared__ char smem[];
    uint32_t sbase = smem_u32(smem);
    int tid = threadIdx.x, wid = tid >> 5, lane = tid & 31;

    int bi = blockIdx.z;
    long long aBase = (long long)(bi / innerN) * sAo + (long long)(bi % innerN) * sAi;
    long long bBase = (long long)(bi / innerN) * sBo + (long long)(bi % innerN) * sBi;
    long long cBase = (long long)(bi / innerN) * sCo + (long long)(bi % innerN) * sCi;
    int m0 = blockIdx.y * 128, n0 = blockIdx.x * 128;

    const bf16* Ahp = Ah + aBase + (long long)m0 * lda;
    const bf16* Alp = Al + aBase + (long long)m0 * lda;
    const bf16* Bhp = Bh + bBase + (long long)n0 * ldb;
    const bf16* Blp = Bl + bBase + (long long)n0 * ldb;

    int lrow = tid >> 2, lch = tid & 3;
    int NC = K >> 5;

    auto load_stage = [&](int c) {
        int s = c % NSTAGE;
        uint32_t st = sbase + s * STAGE_BYTES;
        int k0 = c << 5;
        #pragma unroll
        for (int half = 0; half < 2; half++) {
            int row = lrow + half * 64;
            uint32_t sw = tswz(row, lch);
            long long gk = k0 + lch * 8;
            CP_ASYNC16(st + OFF_AH + sw, Ahp + (long long)row * lda + gk);
            CP_ASYNC16(st + OFF_AL + sw, Alp + (long long)row * lda + gk);
            CP_ASYNC16(st + OFF_BH + sw, Bhp + (long long)row * ldb + gk);
            CP_ASYNC16(st + OFF_BL + sw, Blp + (long long)row * ldb + gk);
        }
    };

    float acc[4][4][4];
    #pragma unroll
    for (int i = 0; i < 4; i++)
        #pragma unroll
        for (int j = 0; j < 4; j++)
            #pragma unroll
            for (int e = 0; e < 4; e++) acc[i][j][e] = 0.f;

    int wm = (wid >> 2) * 64, wn = (wid & 3) * 32;

    load_stage(0); CP_COMMIT();
    if (NC > 1) load_stage(1);
    CP_COMMIT();

    for (int c = 0; c < NC; c++) {
        int s = c % NSTAGE;
        CP_WAIT1();
        __syncthreads();
        if (c + 2 < NC) load_stage(c + 2);
        CP_COMMIT();

        uint32_t st = sbase + s * STAGE_BYTES;
        #pragma unroll
        for (int kk = 0; kk < 2; kk++) {
            uint32_t ah[4][4], al[4][4], bh[4][2], bl[4][2];
            int rA = lane & 15, cA = (kk << 1) + (lane >> 4);
            #pragma unroll
            for (int mt = 0; mt < 4; mt++) {
                uint32_t off = tswz(wm + mt * 16 + rA, cA);
                ldsm4(ah[mt], st + OFF_AH + off);
                ldsm4(al[mt], st + OFF_AL + off);
            }
            int rB = (lane & 7) + ((lane >> 4) << 3);
            int cB = (kk << 1) + ((lane >> 3) & 1);
            #pragma unroll
            for (int ntp = 0; ntp < 2; ntp++) {
                uint32_t off = tswz(wn + ntp * 16 + rB, cB);
                uint32_t t[4];
                ldsm4(t, st + OFF_BH + off);
                bh[2*ntp][0]=t[0]; bh[2*ntp][1]=t[1]; bh[2*ntp+1][0]=t[2]; bh[2*ntp+1][1]=t[3];
                ldsm4(t, st + OFF_BL + off);
                bl[2*ntp][0]=t[0]; bl[2*ntp][1]=t[1]; bl[2*ntp+1][0]=t[2]; bl[2*ntp+1][1]=t[3];
            }
            #pragma unroll
            for (int mt = 0; mt < 4; mt++)
                #pragma unroll
                for (int nt = 0; nt < 4; nt++) {
                    mma16816(acc[mt][nt], ah[mt], bh[nt]);
                    mma16816(acc[mt][nt], ah[mt], bl[nt]);
                    mma16816(acc[mt][nt], al[mt], bh[nt]);
                }
        }
    }

    int qrow = lane >> 2, qcol = (lane & 3) * 2;
    #pragma unroll
    for (int mt = 0; mt < 4; mt++)
        #pragma unroll
        for (int nt = 0; nt < 4; nt++)
            #pragma unroll
            for (int e = 0; e < 4; e++) {
                long long rrow = m0 + wm + mt * 16 + qrow + ((e >> 1) ? 8 : 0);
                int col = n0 + wn + nt * 8 + qcol + (e & 1);
                C[cBase + rrow * ldc + col] = acc[mt][nt][e] * alpha;
            }
}

// ---------------- int8 split GEMM (weight GEMMs) ----------------
// BK = 64 int8 (64 bytes). effective A = sa*(ahi + alo/252), B likewise.
// acc0 = ahi*bhi ; accm = ahi*blo + alo*bhi ; v = sa*sb*(acc0 + accm/252)
__global__ void __launch_bounds__(256, 1) gemm_i8_kernel(
    const int8_t* __restrict__ Ah, const int8_t* __restrict__ Al, const float* __restrict__ sA,
    const int8_t* __restrict__ Bh, const int8_t* __restrict__ Bl, const float* __restrict__ sB,
    float* __restrict__ C,
    int K, int ldc,
    const float* __restrict__ bias, int mode,
    const float* __restrict__ res,
    const float* __restrict__ sst, const float* __restrict__ temb, int modIdx)
{
    extern __shared__ char smem[];
    uint32_t sbase = smem_u32(smem);
    int tid = threadIdx.x, wid = tid >> 5, lane = tid & 31;

    int m0 = blockIdx.y * 128, n0 = blockIdx.x * 128;
    const int8_t* Ahp = Ah + (long long)m0 * K;
    const int8_t* Alp = Al + (long long)m0 * K;
    const int8_t* Bhp = Bh + (long long)n0 * K;
    const int8_t* Blp = Bl + (long long)n0 * K;

    int lrow = tid >> 2, lch = tid & 3;
    int NC = K >> 6;

    auto load_stage = [&](int c) {
        int s = c % NSTAGE;
        uint32_t st = sbase + s * STAGE_BYTES;
        int k0 = c << 6;
        #pragma unroll
        for (int half = 0; half < 2; half++) {
            int row = lrow + half * 64;
            uint32_t sw = tswz(row, lch);
            long long gk = k0 + lch * 16;
            CP_ASYNC16(st + OFF_AH + sw, Ahp + (long long)row * K + gk);
            CP_ASYNC16(st + OFF_AL + sw, Alp + (long long)row * K + gk);
            CP_ASYNC16(st + OFF_BH + sw, Bhp + (long long)row * K + gk);
            CP_ASYNC16(st + OFF_BL + sw, Blp + (long long)row * K + gk);
        }
    };

    int acc0[4][4][4], accm[4][4][4];
    #pragma unroll
    for (int i = 0; i < 4; i++)
        #pragma unroll
        for (int j = 0; j < 4; j++)
            #pragma unroll
            for (int e = 0; e < 4; e++) { acc0[i][j][e] = 0; accm[i][j][e] = 0; }

    int wm = (wid >> 2) * 64, wn = (wid & 3) * 32;

    load_stage(0); CP_COMMIT();
    if (NC > 1) load_stage(1);
    CP_COMMIT();

    for (int c = 0; c < NC; c++) {
        int s = c % NSTAGE;
        CP_WAIT1();
        __syncthreads();
        if (c + 2 < NC) load_stage(c + 2);
        CP_COMMIT();

        uint32_t st = sbase + s * STAGE_BYTES;
        #pragma unroll
        for (int kk = 0; kk < 2; kk++) {     // each kk = 32 int8 of k (2 chunks)
            uint32_t ah[4][4], al[4][4], bh[4][2], bl[4][2];
            int rA = lane & 15, cA = (kk << 1) + (lane >> 4);
            #pragma unroll
            for (int mt = 0; mt < 4; mt++) {
                uint32_t off = tswz(wm + mt * 16 + rA, cA);
                ldsm4(ah[mt], st + OFF_AH + off);
                ldsm4(al[mt], st + OFF_AL + off);
            }
            int rB = (lane & 7) + ((lane >> 4) << 3);
            int cB = (kk << 1) + ((lane >> 3) & 1);
            #pragma unroll
            for (int ntp = 0; ntp < 2; ntp++) {
                uint32_t off = tswz(wn + ntp * 16 + rB, cB);
                uint32_t t[4];
                ldsm4(t, st + OFF_BH + off);
                bh[2*ntp][0]=t[0]; bh[2*ntp][1]=t[1]; bh[2*ntp+1][0]=t[2]; bh[2*ntp+1][1]=t[3];
                ldsm4(t, st + OFF_BL + off);
                bl[2*ntp][0]=t[0]; bl[2*ntp][1]=t[1]; bl[2*ntp+1][0]=t[2]; bl[2*ntp+1][1]=t[3];
            }
            #pragma unroll
            for (int mt = 0; mt < 4; mt++)
                #pragma unroll
                for (int nt = 0; nt < 4; nt++) {
                    mma16832i8(acc0[mt][nt], ah[mt], bh[nt]);
                    mma16832i8(accm[mt][nt], ah[mt], bl[nt]);
                    mma16832i8(accm[mt][nt], al[mt], bh[nt]);
                }
        }
    }

    // ---- epilogue with dequant ----
    int qrow = lane >> 2, qcol = (lane & 3) * 2;
    #pragma unroll
    for (int mt = 0; mt < 4; mt++) {
        #pragma unroll
        for (int nt = 0; nt < 4; nt++) {
            #pragma unroll
            for (int e = 0; e < 4; e++) {
                long long rrow = m0 + wm + mt * 16 + qrow + ((e >> 1) ? 8 : 0);
                int col = n0 + wn + nt * 8 + qcol + (e & 1);
                float v = sA[rrow] * sB[col] *
                          ((float)acc0[mt][nt][e] + (float)accm[mt][nt][e] * (1.0f / 252.0f));
                if (bias) v += bias[col];
                if (mode == 1) v = fast_gelu(v);
                long long ci = rrow * (long long)ldc + col;
                if (mode == 2) {
                    int b_ = (int)(rrow >> 11);   // rows per batch = 2048
                    float g = sst[(long long)modIdx * D + col] +
                              temb[((long long)b_ * 6 + modIdx) * D + col];
                    v = res[ci] + g * v;
                } else if (mode == 3) {
                    v = res[ci] + v;
                }
                C[ci] = v;
            }
        }
    }
}

// ---------------- host helpers ----------------
static void gemm_bf16(const bf16* Ah, const bf16* Al, const bf16* Bh, const bf16* Bl,
                      float* C, int M, int N, int K, int lda, int ldb, int ldc,
                      long long sAo, long long sAi, long long sBo, long long sBi,
                      long long sCo, long long sCi, int innerN, int nbatch, float alpha)
{
    dim3 grid(N / 128, M / 128, nbatch), block(256);
    gemm_bf16_kernel<<<grid, block, GEMM_SMEM>>>(
        Ah, Al, Bh, Bl, C, K, lda, ldb, ldc,
        sAo, sAi, sBo, sBi, sCo, sCi, innerN, alpha);
}

static void gemm_i8(const int8_t* Ah, const int8_t* Al, const float* sA,
                    const int8_t* Bh, const int8_t* Bl, const float* sB,
                    float* C, int M, int N, int K, int ldc,
                    const float* bias, int mode,
                    const float* res, const float* sst, const float* temb, int modIdx)
{
    dim3 grid(N / 128, M / 128, 1), block(256);
    gemm_i8_kernel<<<grid, block, GEMM_SMEM>>>(
        Ah, Al, sA, Bh, Bl, sB, C, K, ldc, bias, mode, res, sst, temb, modIdx);
}

#define GETP(sym) ({ void* _p; cudaGetSymbolAddress(&_p, sym); _p; })

extern "C" void kernel_launch(void* const* d_in, const int* in_sizes, int n_in,
                              void* d_out, int out_size)
{
    const float* h    = (const float*)d_in[0];
    const float* enc  = (const float*)d_in[1];
    const float* temb = (const float*)d_in[2];
    const float* rcos = (const float*)d_in[3];
    const float* rsin = (const float*)d_in[4];
    const float* sst  = (const float*)d_in[5];
    const float* w_qkv = (const float*)d_in[6];
    const float* b_qkv = (const float*)d_in[7];
    const float* rms_q1 = (const float*)d_in[8];
    const float* rms_k1 = (const float*)d_in[9];
    const float* w_o1 = (const float*)d_in[10];
    const float* b_o1 = (const float*)d_in[11];
    const float* ln2_g = (const float*)d_in[12];
    const float* ln2_b = (const float*)d_in[13];
    const float* w_q2 = (const float*)d_in[14];
    const float* b_q2 = (const float*)d_in[15];
    const float* w_kv2 = (const float*)d_in[16];
    const float* b_kv2 = (const float*)d_in[17];
    const float* rms_q2 = (const float*)d_in[18];
    const float* rms_k2 = (const float*)d_in[19];
    const float* w_o2 = (const float*)d_in[20];
    const float* b_o2 = (const float*)d_in[21];
    const float* w_ff1 = (const float*)d_in[22];
    const float* b_ff1 = (const float*)d_in[23];
    const float* w_ff2 = (const float*)d_in[24];
    const float* b_ff2 = (const float*)d_in[25];
    float* out = (float*)d_out;

    cudaFuncSetAttribute(gemm_bf16_kernel, cudaFuncAttributeMaxDynamicSharedMemorySize, GEMM_SMEM);
    cudaFuncSetAttribute(gemm_i8_kernel,  cudaFuncAttributeMaxDynamicSharedMemorySize, GEMM_SMEM);

    float* pqkv = (float*)GETP(g_qkv);
    float* pkv2 = (float*)GETP(g_kv2);
    float* ph1  = (float*)GETP(g_h1);
    float* ph2  = (float*)GETP(g_h2);
    float* pattn= (float*)GETP(g_attn);
    float* pmid = (float*)GETP(g_mid);
    float* plog = (float*)GETP(g_logits);
    bf16 *qh=(bf16*)GETP(g_qh), *ql=(bf16*)GETP(g_ql);
    bf16 *kh=(bf16*)GETP(g_kh), *kl=(bf16*)GETP(g_kl);
    bf16 *vh=(bf16*)GETP(g_vh), *vl=(bf16*)GETP(g_vl);
    bf16 *Ph=(bf16*)GETP(g_Ph), *Pl=(bf16*)GETP(g_Pl);
    int8_t *a8h=(int8_t*)GETP(g_a8h), *a8l=(int8_t*)GETP(g_a8l);
    float  *sact=(float*)GETP(g_sact);
    int8_t *e8h=(int8_t*)GETP(g_e8h), *e8l=(int8_t*)GETP(g_e8l);
    float  *se=(float*)GETP(g_se);
    int8_t *wqkvh=(int8_t*)GETP(g_wqkv8h), *wqkvl=(int8_t*)GETP(g_wqkv8l);
    float  *swqkv=(float*)GETP(g_swqkv);
    int8_t *wo1h=(int8_t*)GETP(g_wo18h), *wo1l=(int8_t*)GETP(g_wo18l);
    float  *swo1=(float*)GETP(g_swo1);
    int8_t *wq2h=(int8_t*)GETP(g_wq28h), *wq2l=(int8_t*)GETP(g_wq28l);
    float  *swq2=(float*)GETP(g_swq2);
    int8_t *wkv2h=(int8_t*)GETP(g_wkv28h), *wkv2l=(int8_t*)GETP(g_wkv28l);
    float  *swkv2=(float*)GETP(g_swkv2);
    int8_t *wo2h=(int8_t*)GETP(g_wo28h), *wo2l=(int8_t*)GETP(g_wo28l);
    float  *swo2=(float*)GETP(g_swo2);
    int8_t *wff1h=(int8_t*)GETP(g_wff18h), *wff1l=(int8_t*)GETP(g_wff18l);
    float  *swff1=(float*)GETP(g_swff1);
    int8_t *wff2h=(int8_t*)GETP(g_wff28h), *wff2l=(int8_t*)GETP(g_wff28l);
    float  *swff2=(float*)GETP(g_swff2);

    const float scale = 0.08838834764831845f;
    const long long uQ  = (long long)SSELF * HDIM;
    const long long uL  = (long long)SSELF * SSELF;
    const long long uV  = (long long)HDIM * SSELF;
    const long long uK2 = (long long)SCROSS * HDIM;
    const long long uL2 = (long long)SSELF * SCROSS;
    const long long uV2 = (long long)HDIM * SCROSS;

    // ---- weight quantization ----
    quant8_kernel<<<3 * D, 256>>>(w_qkv, D, wqkvh, wqkvl, swqkv);
    quant8_kernel<<<D, 256>>>(w_o1, D, wo1h, wo1l, swo1);
    quant8_kernel<<<D, 256>>>(w_q2, D, wq2h, wq2l, swq2);
    quant8_kernel<<<2 * D, 256>>>(w_kv2, D, wkv2h, wkv2l, swkv2);
    quant8_kernel<<<D, 256>>>(w_o2, D, wo2h, wo2l, swo2);
    quant8_kernel<<<FFND, 256>>>(w_ff1, D, wff1h, wff1l, swff1);
    quant8_kernel<<<D, 256>>>(w_ff2, FFND, wff2h, wff2l, swff2);
    quant8_kernel<<<TOKC, 256>>>(enc, D, e8h, e8l, se);

    // 1) x = modulated LN(h) -> int8
    ln_q8_kernel<<<TOK, 256>>>(h, a8h, a8l, sact, nullptr, nullptr, sst, temb, 0, 1, SSELF);
    // 2) qkv = x @ w_qkv^T + b
    gemm_i8(a8h, a8l, sact, wqkvh, wqkvl, swqkv, pqkv, TOK, 3 * D, D, 3 * D,
            b_qkv, 0, nullptr, nullptr, nullptr, 0);
    // 3-5) heads (bf16)
    rms_heads_kernel<<<TOK, 256>>>(pqkv, 3 * D, 0, rms_q1, qh, ql, SSELF, rcos, rsin);
    rms_heads_kernel<<<TOK, 256>>>(pqkv, 3 * D, D, rms_k1, kh, kl, SSELF, rcos, rsin);
    vtrans_kernel<<<2048, 256>>>(pqkv, 3 * D, 2 * D, vh, vl, SSELF, (long long)TOK * D);
    // 6) logits
    gemm_bf16(qh, ql, kh, kl, plog, SSELF, SSELF, HDIM, HDIM, HDIM, SSELF,
              NH * uQ, uQ, NH * uQ, uQ, NH * uL, uL, NH, BH, scale);
    // 7) softmax
    softmax_kernel<<<BH * SSELF, 256>>>(plog, Ph, Pl, SSELF);
    // 8) attn = P @ V -> merged fp32
    gemm_bf16(Ph, Pl, vh, vl, pattn, SSELF, HDIM, SSELF, SSELF, SSELF, D,
              NH * uL, uL, NH * uV, uV, (long long)SSELF * D, HDIM, NH, BH, 1.f);
    // 9) quantize attn, o1: h1 = h + gate_sa * (attn W_o1^T + b)
    quant8_kernel<<<TOK, 256>>>(pattn, D, a8h, a8l, sact);
    gemm_i8(a8h, a8l, sact, wo1h, wo1l, swo1, ph1, TOK, D, D, D,
            b_o1, 2, h, sst, temb, 2);
    // 10) x2 = LN(h1, g, b) -> int8
    ln_q8_kernel<<<TOK, 256>>>(ph1, a8h, a8l, sact, ln2_g, ln2_b, nullptr, nullptr, 0, 0, SSELF);
    // 11) q2lin
    gemm_i8(a8h, a8l, sact, wq2h, wq2l, swq2, pqkv, TOK, D, D, D,
            b_q2, 0, nullptr, nullptr, nullptr, 0);
    rms_heads_kernel<<<TOK, 256>>>(pqkv, D, 0, rms_q2, qh, ql, SSELF, nullptr, nullptr);
    // 13) kv2 = enc @ w_kv2^T + b
    gemm_i8(e8h, e8l, se, wkv2h, wkv2l, swkv2, pkv2, TOKC, 2 * D, D, 2 * D,
            b_kv2, 0, nullptr, nullptr, nullptr, 0);
    rms_heads_kernel<<<TOKC, 256>>>(pkv2, 2 * D, 0, rms_k2, kh, kl, SCROSS, nullptr, nullptr);
    vtrans_kernel<<<512, 256>>>(pkv2, 2 * D, D, vh, vl, SCROSS, (long long)TOKC * D);
    // 16) logits2
    gemm_bf16(qh, ql, kh, kl, plog, SSELF, SCROSS, HDIM, HDIM, HDIM, SCROSS,
              NH * uQ, uQ, NH * uK2, uK2, NH * uL2, uL2, NH, BH, scale);
    softmax_kernel<<<BH * SSELF, 256>>>(plog, Ph, Pl, SCROSS);
    // 18) attn2
    gemm_bf16(Ph, Pl, vh, vl, pattn, SSELF, HDIM, SCROSS, SCROSS, SCROSS, D,
              NH * uL2, uL2, NH * uV2, uV2, (long long)SSELF * D, HDIM, NH, BH, 1.f);
    // 19) quantize attn2; h2 = h1 + attn2 W_o2^T + b
    quant8_kernel<<<TOK, 256>>>(pattn, D, a8h, a8l, sact);
    gemm_i8(a8h, a8l, sact, wo2h, wo2l, swo2, ph2, TOK, D, D, D,
            b_o2, 3, ph1, nullptr, nullptr, 0);
    // 20) xff -> int8
    ln_q8_kernel<<<TOK, 256>>>(ph2, a8h, a8l, sact, nullptr, nullptr, sst, temb, 3, 4, SSELF);
    // 21) mid = gelu(xff W_ff1^T + b) fp32
    gemm_i8(a8h, a8l, sact, wff1h, wff1l, swff1, pmid, TOK, FFND, D, FFND,
            b_ff1, 1, nullptr, nullptr, nullptr, 0);
    // 22) quantize mid; out = h2 + gate_ff * (mid W_ff2^T + b)
    quant8_kernel<<<TOK, 256>>>(pmid, FFND, a8h, a8l, sact);
    gemm_i8(a8h, a8l, sact, wff2h, wff2l, swff2, out, TOK, D, FFND, D,
            b_ff2, 2, ph2, sst, temb, 5);

    (void)in_sizes; (void)n_in; (void)out_size;
}

// round 6
// speedup vs baseline: 2.5051x; 2.5051x over previous
#include <cuda_runtime.h>
#include <cuda_fp16.h>
#include <cstdint>
#include <math.h>

// ---------------- problem constants ----------------
#define D      2560
#define SSELF  2048
#define SCROSS 512
#define NB     2
#define NH     20
#define HDIM   128
#define FFND   10240
#define TOK    4096
#define TOKC   1024
#define BH     40
#define EPSV   1e-6f

typedef __half f16;

// ---------------- scratch (device globals) ----------------
__device__ float g_qkv [(size_t)TOK * 3 * D];
__device__ float g_kv2 [(size_t)TOKC * 2 * D];
__device__ float g_h1  [(size_t)TOK * D];
__device__ float g_h2  [(size_t)TOK * D];
__device__ float g_logits[(size_t)BH * SSELF * SSELF];

// A-side split buffers (hi+lo fp16)
__device__ f16 g_xh[(size_t)TOK * D],  g_xl[(size_t)TOK * D];
__device__ f16 g_qh[(size_t)TOK * D],  g_ql[(size_t)TOK * D];
__device__ f16 g_ah[(size_t)TOK * D],  g_al[(size_t)TOK * D];
__device__ f16 g_mh[(size_t)TOK * FFND], g_ml[(size_t)TOK * FFND];
__device__ f16 g_Ph[(size_t)BH * SSELF * SSELF], g_Pl[(size_t)BH * SSELF * SSELF];
__device__ f16 g_ench[(size_t)TOKC * D], g_encl[(size_t)TOKC * D];

// B-side single-fp16 buffers
__device__ f16 g_kb[(size_t)TOK * D];
__device__ f16 g_vb[(size_t)TOK * D];
__device__ f16 g_wqkv[(size_t)3 * D * D];
__device__ f16 g_wo1 [(size_t)D * D];
__device__ f16 g_wq2 [(size_t)D * D];
__device__ f16 g_wkv2[(size_t)2 * D * D];
__device__ f16 g_wo2 [(size_t)D * D];
__device__ f16 g_wff1[(size_t)FFND * D];
__device__ f16 g_wff2[(size_t)D * FFND];

// ---------------- small helpers ----------------
__device__ __forceinline__ void split2h(float v, f16& h, f16& l) {
    h = __float2half_rn(v);
    l = __float2half_rn(v - __half2float(h));
}

__device__ __forceinline__ float fast_gelu(float x) {
    float u = 0.7978845608028654f * (x + 0.044715f * x * x * x);
    float t = 1.0f - 2.0f / (1.0f + __expf(2.0f * u));
    return 0.5f * x * (1.0f + t);
}

__device__ __forceinline__ uint32_t smem_u32(const void* p) {
    uint32_t a;
    asm("{ .reg .u64 t; cvta.to.shared.u64 t, %1; cvt.u32.u64 %0, t; }" : "=r"(a) : "l"(p));
    return a;
}

#define CP_ASYNC16(dst, src) \
    asm volatile("cp.async.cg.shared.global [%0], [%1], 16;" :: "r"(dst), "l"(src))
#define CP_COMMIT() asm volatile("cp.async.commit_group;" ::: "memory")
#define CP_WAIT1()  asm volatile("cp.async.wait_group 1;" ::: "memory")

__device__ __forceinline__ void ldsm4(uint32_t* r, uint32_t addr) {
    asm volatile("ldmatrix.sync.aligned.m8n8.x4.shared.b16 {%0,%1,%2,%3}, [%4];"
        : "=r"(r[0]), "=r"(r[1]), "=r"(r[2]), "=r"(r[3]) : "r"(addr));
}

__device__ __forceinline__ void mma16816h(float* c, const uint32_t* a, const uint32_t* b) {
    asm volatile("mma.sync.aligned.m16n8k16.row.col.f32.f16.f16.f32 "
        "{%0,%1,%2,%3}, {%4,%5,%6,%7}, {%8,%9}, {%0,%1,%2,%3};"
        : "+f"(c[0]), "+f"(c[1]), "+f"(c[2]), "+f"(c[3])
        : "r"(a[0]), "r"(a[1]), "r"(a[2]), "r"(a[3]), "r"(b[0]), "r"(b[1]));
}

// ---------------- reductions ----------------
__device__ __forceinline__ float blockReduceSum(float v) {
    __shared__ float sh[32];
    int lane = threadIdx.x & 31, wid = threadIdx.x >> 5;
    #pragma unroll
    for (int o = 16; o > 0; o >>= 1) v += __shfl_xor_sync(0xffffffffu, v, o);
    __syncthreads();
    if (lane == 0) sh[wid] = v;
    __syncthreads();
    int nw = blockDim.x >> 5;
    float r = (threadIdx.x < nw) ? sh[threadIdx.x] : 0.0f;
    if (wid == 0) {
        #pragma unroll
        for (int o = 16; o > 0; o >>= 1) r += __shfl_xor_sync(0xffffffffu, r, o);
        if (lane == 0) sh[0] = r;
    }
    __syncthreads();
    return sh[0];
}

__device__ __forceinline__ float blockReduceMax(float v) {
    __shared__ float sh[32];
    int lane = threadIdx.x & 31, wid = threadIdx.x >> 5;
    #pragma unroll
    for (int o = 16; o > 0; o >>= 1) v = fmaxf(v, __shfl_xor_sync(0xffffffffu, v, o));
    __syncthreads();
    if (lane == 0) sh[wid] = v;
    __syncthreads();
    int nw = blockDim.x >> 5;
    float r = (threadIdx.x < nw) ? sh[threadIdx.x] : -3.4e38f;
    if (wid == 0) {
        #pragma unroll
        for (int o = 16; o > 0; o >>= 1) r = fmaxf(r, __shfl_xor_sync(0xffffffffu, r, o));
        if (lane == 0) sh[0] = r;
    }
    __syncthreads();
    return sh[0];
}

// ---------------- elementwise producers ----------------
__global__ void __launch_bounds__(256) ln_kernel(
    const float* __restrict__ in, f16* __restrict__ oh, f16* __restrict__ ol,
    const float* __restrict__ gamma, const float* __restrict__ beta,
    const float* __restrict__ sst, const float* __restrict__ temb,
    int iShift, int iScale, int rowsPerB)
{
    long long r = blockIdx.x;
    const float* x = in + r * D;
    float s1 = 0.f, s2 = 0.f;
    for (int d = threadIdx.x; d < D; d += 256) { float v = x[d]; s1 += v; s2 += v * v; }
    s1 = blockReduceSum(s1);
    s2 = blockReduceSum(s2);
    float mean = s1 * (1.0f / D);
    float var  = s2 * (1.0f / D) - mean * mean;
    float rstd = rsqrtf(var + EPSV);
    int b = (int)(r / rowsPerB);
    for (int d = threadIdx.x; d < D; d += 256) {
        float y = (x[d] - mean) * rstd;
        if (sst) {
            float sc = sst[iScale * D + d] + temb[((long long)b * 6 + iScale) * D + d];
            float sh = sst[iShift * D + d] + temb[((long long)b * 6 + iShift) * D + d];
            y = y * (1.f + sc) + sh;
        } else if (gamma) {
            y = y * gamma[d] + beta[d];
        }
        f16 hh, ll; split2h(y, hh, ll);
        oh[r * D + d] = hh; ol[r * D + d] = ll;
    }
}

// RMS + optional rope; writes hi (+lo if ol != null) into [B,H,S,HD]
__global__ void __launch_bounds__(256) rms_heads_kernel(
    const float* __restrict__ in, int ldin, int off,
    const float* __restrict__ w, f16* __restrict__ oh, f16* __restrict__ ol, int Srows,
    const float* __restrict__ rcos, const float* __restrict__ rsin)
{
    long long r = blockIdx.x;
    int b = (int)(r / Srows), s = (int)(r % Srows);
    const float* x = in + r * ldin + off;
    float s2 = 0.f;
    for (int d = threadIdx.x; d < D; d += 256) { float v = x[d]; s2 += v * v; }
    s2 = blockReduceSum(s2);
    float rms = rsqrtf(s2 * (1.0f / D) + EPSV);
    for (int d = threadIdx.x; d < D; d += 256) {
        int h = d >> 7, dd = d & 127;
        float v = x[d] * rms * w[d];
        if (rcos) {
            int pd = (dd < 64) ? d + 64 : d - 64;
            float vp = x[pd] * rms * w[pd];
            float c = rcos[s * HDIM + dd], sn = rsin[s * HDIM + dd];
            v = (dd < 64) ? (v * c - vp * sn) : (v * c + vp * sn);
        }
        long long oi = (((long long)(b * NH + h)) * Srows + s) * HDIM + dd;
        if (ol) {
            f16 hh, ll; split2h(v, hh, ll);
            oh[oi] = hh; ol[oi] = ll;
        } else {
            oh[oi] = __float2half_rn(v);
        }
    }
}

// V transpose to [B,H,HD,Srows], single fp16
__global__ void __launch_bounds__(256) vtrans_kernel(
    const float* __restrict__ in, int ldin, int off,
    f16* __restrict__ ob, int Srows, long long total)
{
    for (long long i = blockIdx.x * 256LL + threadIdx.x; i < total; i += (long long)gridDim.x * 256) {
        long long r = i / D; int col = (int)(i % D);
        int h = col >> 7, d = col & 127;
        int b = (int)(r / Srows), s = (int)(r % Srows);
        ob[(((long long)(b * NH + h)) * HDIM + d) * Srows + s] =
            __float2half_rn(in[r * ldin + off + col]);
    }
}

__global__ void __launch_bounds__(256) softmax_kernel(
    float* __restrict__ p, f16* __restrict__ oh, f16* __restrict__ ol, int len)
{
    long long r = blockIdx.x;
    float* x = p + r * (long long)len;
    float mx = -3.4e38f;
    for (int d = threadIdx.x; d < len; d += 256) mx = fmaxf(mx, x[d]);
    mx = blockReduceMax(mx);
    float sum = 0.f;
    for (int d = threadIdx.x; d < len; d += 256) { float e = __expf(x[d] - mx); x[d] = e; sum += e; }
    sum = blockReduceSum(sum);
    float inv = 1.0f / sum;
    for (int d = threadIdx.x; d < len; d += 256) {
        float v = x[d] * inv;
        f16 hh, ll; split2h(v, hh, ll);
        oh[r * (long long)len + d] = hh; ol[r * (long long)len + d] = ll;
    }
}

// fp32 -> fp16 (B-side weights)
__global__ void __launch_bounds__(256) conv_kernel(
    const float* __restrict__ in, f16* __restrict__ ob, long long n)
{
    for (long long i = blockIdx.x * 256LL + threadIdx.x; i < n; i += (long long)gridDim.x * 256)
        ob[i] = __float2half_rn(in[i]);
}

// fp32 -> fp16 hi/lo pair (A-side, e.g. encoder)
__global__ void __launch_bounds__(256) split_kernel(
    const float* __restrict__ in, f16* __restrict__ oh, f16* __restrict__ ol, long long n)
{
    for (long long i = blockIdx.x * 256LL + threadIdx.x; i < n; i += (long long)gridDim.x * 256) {
        f16 h, l; split2h(in[i], h, l);
        oh[i] = h; ol[i] = l;
    }
}

// ---------------- fp16 2-product GEMM ----------------
// C = alpha * (Ah+Al) @ Bh^T (+bias +epilogue); A [M,K] hi/lo fp16, B [N,K] fp16
// BM=BN=128, BK=32, 3-stage cp.async, 8 warps (64x32 per warp)
#define STAGE_BYTES 24576
#define OFF_AH 0
#define OFF_AL 8192
#define OFF_BH 16384
#define NSTAGE 3
#define GEMM_SMEM (NSTAGE * STAGE_BYTES)

__device__ __forceinline__ uint32_t tswz(int row, int chunk) {
    return (uint32_t)(row * 64 + ((chunk ^ (row & 3)) << 4));
}

__global__ void __launch_bounds__(256, 1) gemm_h2_kernel(
    const f16* __restrict__ Ah, const f16* __restrict__ Al,
    const f16* __restrict__ Bh,
    float* __restrict__ C, f16* __restrict__ Ch, f16* __restrict__ Cl,
    int K, int lda, int ldb, int ldc,
    long long sAo, long long sAi, long long sBo, long long sBi,
    long long sCo, long long sCi, int innerN,
    const float* __restrict__ bias, float alpha, int mode,
    const float* __restrict__ res,
    const float* __restrict__ sst, const float* __restrict__ temb,
    int modIdx)
{
    extern __shared__ char smem[];
    uint32_t sbase = smem_u32(smem);
    int tid = threadIdx.x, wid = tid >> 5, lane = tid & 31;

    int bi = blockIdx.z;
    long long aBase = (long long)(bi / innerN) * sAo + (long long)(bi % innerN) * sAi;
    long long bBase = (long long)(bi / innerN) * sBo + (long long)(bi % innerN) * sBi;
    long long cBase = (long long)(bi / innerN) * sCo + (long long)(bi % innerN) * sCi;
    int m0 = blockIdx.y * 128, n0 = blockIdx.x * 128;

    const f16* Ahp = Ah + aBase + (long long)m0 * lda;
    const f16* Alp = Al + aBase + (long long)m0 * lda;
    const f16* Bhp = Bh + bBase + (long long)n0 * ldb;

    int lrow = tid >> 2, lch = tid & 3;
    int NC = K >> 5;

    auto load_stage = [&](int c) {
        int s = c % NSTAGE;
        uint32_t st = sbase + s * STAGE_BYTES;
        int k0 = c << 5;
        #pragma unroll
        for (int half = 0; half < 2; half++) {
            int row = lrow + half * 64;
            uint32_t sw = tswz(row, lch);
            long long gk = k0 + lch * 8;
            CP_ASYNC16(st + OFF_AH + sw, Ahp + (long long)row * lda + gk);
            CP_ASYNC16(st + OFF_AL + sw, Alp + (long long)row * lda + gk);
            CP_ASYNC16(st + OFF_BH + sw, Bhp + (long long)row * ldb + gk);
        }
    };

    float acc[4][4][4];
    #pragma unroll
    for (int i = 0; i < 4; i++)
        #pragma unroll
        for (int j = 0; j < 4; j++)
            #pragma unroll
            for (int e = 0; e < 4; e++) acc[i][j][e] = 0.f;

    int wm = (wid >> 2) * 64, wn = (wid & 3) * 32;

    load_stage(0); CP_COMMIT();
    if (NC > 1) load_stage(1);
    CP_COMMIT();

    for (int c = 0; c < NC; c++) {
        int s = c % NSTAGE;
        CP_WAIT1();
        __syncthreads();
        if (c + 2 < NC) load_stage(c + 2);
        CP_COMMIT();

        uint32_t st = sbase + s * STAGE_BYTES;
        #pragma unroll
        for (int kk = 0; kk < 2; kk++) {
            uint32_t ah[4][4], al[4][4], bh[4][2];
            int rA = lane & 15, cA = (kk << 1) + (lane >> 4);
            #pragma unroll
            for (int mt = 0; mt < 4; mt++) {
                uint32_t off = tswz(wm + mt * 16 + rA, cA);
                ldsm4(ah[mt], st + OFF_AH + off);
                ldsm4(al[mt], st + OFF_AL + off);
            }
            int rB = (lane & 7) + ((lane >> 4) << 3);
            int cB = (kk << 1) + ((lane >> 3) & 1);
            #pragma unroll
            for (int ntp = 0; ntp < 2; ntp++) {
                uint32_t off = tswz(wn + ntp * 16 + rB, cB);
                uint32_t t[4];
                ldsm4(t, st + OFF_BH + off);
                bh[2*ntp][0]=t[0]; bh[2*ntp][1]=t[1]; bh[2*ntp+1][0]=t[2]; bh[2*ntp+1][1]=t[3];
            }
            #pragma unroll
            for (int mt = 0; mt < 4; mt++)
                #pragma unroll
                for (int nt = 0; nt < 4; nt++) {
                    mma16816h(acc[mt][nt], ah[mt], bh[nt]);
                    mma16816h(acc[mt][nt], al[mt], bh[nt]);
                }
        }
    }

    // ---- epilogue ----
    int qrow = lane >> 2, qcol = (lane & 3) * 2;
    #pragma unroll
    for (int mt = 0; mt < 4; mt++) {
        #pragma unroll
        for (int nt = 0; nt < 4; nt++) {
            #pragma unroll
            for (int e = 0; e < 4; e++) {
                long long rrow = m0 + wm + mt * 16 + qrow + ((e >> 1) ? 8 : 0);
                int col = n0 + wn + nt * 8 + qcol + (e & 1);
                float v = acc[mt][nt][e] * alpha;
                if (bias) v += bias[col];
                if (mode == 1) v = fast_gelu(v);
                long long ci = cBase + rrow * ldc + col;
                if (mode == 2) {
                    int b_ = (int)(rrow >> 11);  // 2048 rows per batch
                    float g = sst[(long long)modIdx * D + col] +
                              temb[((long long)b_ * 6 + modIdx) * D + col];
                    v = res[ci] + g * v;
                } else if (mode == 3) {
                    v = res[ci] + v;
                }
                if (C) C[ci] = v;
                if (Ch) {
                    f16 hh, ll; split2h(v, hh, ll);
                    Ch[ci] = hh; Cl[ci] = ll;
                }
            }
        }
    }
}

// ---------------- host launch helper ----------------
static void gemm(const f16* Ah, const f16* Al, const f16* Bh,
                 float* C, f16* Ch, f16* Cl,
                 int M, int N, int K, int lda, int ldb, int ldc,
                 long long sAo, long long sAi, long long sBo, long long sBi,
                 long long sCo, long long sCi, int innerN, int nbatch,
                 const float* bias, float alpha, int mode,
                 const float* res, const float* sst, const float* temb,
                 int modIdx)
{
    dim3 grid(N / 128, M / 128, nbatch), block(256);
    gemm_h2_kernel<<<grid, block, GEMM_SMEM>>>(
        Ah, Al, Bh, C, Ch, Cl, K, lda, ldb, ldc,
        sAo, sAi, sBo, sBi, sCo, sCi, innerN,
        bias, alpha, mode, res, sst, temb, modIdx);
}

#define GETP(sym) ({ void* _p; cudaGetSymbolAddress(&_p, sym); _p; })

extern "C" void kernel_launch(void* const* d_in, const int* in_sizes, int n_in,
                              void* d_out, int out_size)
{
    const float* h    = (const float*)d_in[0];
    const float* enc  = (const float*)d_in[1];
    const float* temb = (const float*)d_in[2];
    const float* rcos = (const float*)d_in[3];
    const float* rsin = (const float*)d_in[4];
    const float* sst  = (const float*)d_in[5];
    const float* w_qkv = (const float*)d_in[6];
    const float* b_qkv = (const float*)d_in[7];
    const float* rms_q1 = (const float*)d_in[8];
    const float* rms_k1 = (const float*)d_in[9];
    const float* w_o1 = (const float*)d_in[10];
    const float* b_o1 = (const float*)d_in[11];
    const float* ln2_g = (const float*)d_in[12];
    const float* ln2_b = (const float*)d_in[13];
    const float* w_q2 = (const float*)d_in[14];
    const float* b_q2 = (const float*)d_in[15];
    const float* w_kv2 = (const float*)d_in[16];
    const float* b_kv2 = (const float*)d_in[17];
    const float* rms_q2 = (const float*)d_in[18];
    const float* rms_k2 = (const float*)d_in[19];
    const float* w_o2 = (const float*)d_in[20];
    const float* b_o2 = (const float*)d_in[21];
    const float* w_ff1 = (const float*)d_in[22];
    const float* b_ff1 = (const float*)d_in[23];
    const float* w_ff2 = (const float*)d_in[24];
    const float* b_ff2 = (const float*)d_in[25];
    float* out = (float*)d_out;

    cudaFuncSetAttribute(gemm_h2_kernel, cudaFuncAttributeMaxDynamicSharedMemorySize, GEMM_SMEM);

    float* pqkv = (float*)GETP(g_qkv);
    float* pkv2 = (float*)GETP(g_kv2);
    float* ph1  = (float*)GETP(g_h1);
    float* ph2  = (float*)GETP(g_h2);
    float* plog = (float*)GETP(g_logits);
    f16 *xh=(f16*)GETP(g_xh), *xl=(f16*)GETP(g_xl);
    f16 *qh=(f16*)GETP(g_qh), *ql=(f16*)GETP(g_ql);
    f16 *ath=(f16*)GETP(g_ah), *atl=(f16*)GETP(g_al);
    f16 *mh=(f16*)GETP(g_mh), *ml=(f16*)GETP(g_ml);
    f16 *Ph=(f16*)GETP(g_Ph), *Pl=(f16*)GETP(g_Pl);
    f16 *ench=(f16*)GETP(g_ench), *encl=(f16*)GETP(g_encl);
    f16 *kb=(f16*)GETP(g_kb), *vb=(f16*)GETP(g_vb);
    f16 *wqkv=(f16*)GETP(g_wqkv);
    f16 *wo1=(f16*)GETP(g_wo1);
    f16 *wq2=(f16*)GETP(g_wq2);
    f16 *wkv2=(f16*)GETP(g_wkv2);
    f16 *wo2=(f16*)GETP(g_wo2);
    f16 *wff1=(f16*)GETP(g_wff1);
    f16 *wff2=(f16*)GETP(g_wff2);

    const float scale = 0.08838834764831845f;
    const long long uQ  = (long long)SSELF * HDIM;
    const long long uL  = (long long)SSELF * SSELF;
    const long long uV  = (long long)HDIM * SSELF;
    const long long uK2 = (long long)SCROSS * HDIM;
    const long long uL2 = (long long)SSELF * SCROSS;
    const long long uV2 = (long long)HDIM * SCROSS;

    // 0) ln ; 1) wqkv convert ; 2) qkv GEMM (profiled launch idx 2)
    ln_kernel<<<TOK, 256>>>(h, xh, xl, nullptr, nullptr, sst, temb, 0, 1, SSELF);
    conv_kernel<<<2048, 256>>>(w_qkv, wqkv, (long long)3 * D * D);
    gemm(xh, xl, wqkv, pqkv, nullptr, nullptr, TOK, 3 * D, D, D, D, 3 * D,
         0,0,0,0,0,0,1,1, b_qkv, 1.f, 0, nullptr, nullptr, nullptr, 0);
    // other weight converts
    conv_kernel<<<1024, 256>>>(w_o1,  wo1,  (long long)D * D);
    conv_kernel<<<1024, 256>>>(w_q2,  wq2,  (long long)D * D);
    conv_kernel<<<1024, 256>>>(w_kv2, wkv2, (long long)2 * D * D);
    conv_kernel<<<1024, 256>>>(w_o2,  wo2,  (long long)D * D);
    conv_kernel<<<2048, 256>>>(w_ff1, wff1, (long long)FFND * D);
    conv_kernel<<<2048, 256>>>(w_ff2, wff2, (long long)D * FFND);
    split_kernel<<<1024, 256>>>(enc, ench, encl, (long long)TOKC * D);
    // heads: q hi/lo, k hi-only (B side), v fp16 transposed
    rms_heads_kernel<<<TOK, 256>>>(pqkv, 3 * D, 0, rms_q1, qh, ql, SSELF, rcos, rsin);
    rms_heads_kernel<<<TOK, 256>>>(pqkv, 3 * D, D, rms_k1, kb, nullptr, SSELF, rcos, rsin);
    vtrans_kernel<<<2048, 256>>>(pqkv, 3 * D, 2 * D, vb, SSELF, (long long)TOK * D);
    // logits = scale * q k^T
    gemm(qh, ql, kb, plog, nullptr, nullptr, SSELF, SSELF, HDIM, HDIM, HDIM, SSELF,
         NH * uQ, uQ, NH * uQ, uQ, NH * uL, uL, NH, BH,
         nullptr, scale, 0, nullptr, nullptr, nullptr, 0);
    softmax_kernel<<<BH * SSELF, 256>>>(plog, Ph, Pl, SSELF);
    // attn = P @ V -> hi/lo fp16 merged [TOK, D]
    gemm(Ph, Pl, vb, nullptr, ath, atl, SSELF, HDIM, SSELF, SSELF, SSELF, D,
         NH * uL, uL, NH * uV, uV, (long long)SSELF * D, HDIM, NH, BH,
         nullptr, 1.f, 0, nullptr, nullptr, nullptr, 0);
    // h1 = h + gate_sa * (attn W_o1^T + b)
    gemm(ath, atl, wo1, ph1, nullptr, nullptr, TOK, D, D, D, D, D,
         0,0,0,0,0,0,1,1, b_o1, 1.f, 2, h, sst, temb, 2);
    // x2 = LN(h1)
    ln_kernel<<<TOK, 256>>>(ph1, xh, xl, ln2_g, ln2_b, nullptr, nullptr, 0, 0, SSELF);
    // q2lin
    gemm(xh, xl, wq2, pqkv, nullptr, nullptr, TOK, D, D, D, D, D,
         0,0,0,0,0,0,1,1, b_q2, 1.f, 0, nullptr, nullptr, nullptr, 0);
    rms_heads_kernel<<<TOK, 256>>>(pqkv, D, 0, rms_q2, qh, ql, SSELF, nullptr, nullptr);
    // kv2 = enc @ w_kv2^T + b
    gemm(ench, encl, wkv2, pkv2, nullptr, nullptr, TOKC, 2 * D, D, D, D, 2 * D,
         0,0,0,0,0,0,1,1, b_kv2, 1.f, 0, nullptr, nullptr, nullptr, 0);
    rms_heads_kernel<<<TOKC, 256>>>(pkv2, 2 * D, 0, rms_k2, kb, nullptr, SCROSS, nullptr, nullptr);
    vtrans_kernel<<<512, 256>>>(pkv2, 2 * D, D, vb, SCROSS, (long long)TOKC * D);
    // logits2
    gemm(qh, ql, kb, plog, nullptr, nullptr, SSELF, SCROSS, HDIM, HDIM, HDIM, SCROSS,
         NH * uQ, uQ, NH * uK2, uK2, NH * uL2, uL2, NH, BH,
         nullptr, scale, 0, nullptr, nullptr, nullptr, 0);
    softmax_kernel<<<BH * SSELF, 256>>>(plog, Ph, Pl, SCROSS);
    // attn2 -> hi/lo
    gemm(Ph, Pl, vb, nullptr, ath, atl, SSELF, HDIM, SCROSS, SCROSS, SCROSS, D,
         NH * uL2, uL2, NH * uV2, uV2, (long long)SSELF * D, HDIM, NH, BH,
         nullptr, 1.f, 0, nullptr, nullptr, nullptr, 0);
    // h2 = h1 + attn2 W_o2^T + b
    gemm(ath, atl, wo2, ph2, nullptr, nullptr, TOK, D, D, D, D, D,
         0,0,0,0,0,0,1,1, b_o2, 1.f, 3, ph1, nullptr, nullptr, 0);
    // xff
    ln_kernel<<<TOK, 256>>>(ph2, xh, xl, nullptr, nullptr, sst, temb, 3, 4, SSELF);
    // mid = gelu(xff W_ff1^T + b) -> hi/lo fp16
    gemm(xh, xl, wff1, nullptr, mh, ml, TOK, FFND, D, D, D, FFND,
         0,0,0,0,0,0,1,1, b_ff1, 1.f, 1, nullptr, nullptr, nullptr, 0);
    // out = h2 + gate_ff * (mid W_ff2^T + b)
    gemm(mh, ml, wff2, out, nullptr, nullptr, TOK, D, FFND, FFND, FFND, D,
         0,0,0,0,0,0,1,1, b_ff2, 1.f, 2, ph2, sst, temb, 5);

    (void)in_sizes; (void)n_in; (void)out_size;
}

// round 7
// speedup vs baseline: 4.3567x; 1.7391x over previous
#include <cuda_runtime.h>
#include <cuda_fp16.h>
#include <cstdint>
#include <math.h>

// ---------------- problem constants ----------------
#define D      2560
#define SSELF  2048
#define SCROSS 512
#define NB     2
#define NH     20
#define HDIM   128
#define FFND   10240
#define TOK    4096
#define TOKC   1024
#define BH     40
#define EPSV   1e-6f

typedef __half f16;

// ---------------- scratch (device globals) ----------------
__device__ float g_qkv [(size_t)TOK * 3 * D];
__device__ float g_kv2 [(size_t)TOKC * 2 * D];
__device__ float g_h1  [(size_t)TOK * D];
__device__ float g_h2  [(size_t)TOK * D];
__device__ float g_logits[(size_t)BH * SSELF * SSELF];

__device__ f16 g_x[(size_t)TOK * D];
__device__ f16 g_q[(size_t)TOK * D];
__device__ f16 g_a[(size_t)TOK * D];
__device__ f16 g_m[(size_t)TOK * FFND];
__device__ f16 g_P[(size_t)BH * SSELF * SSELF];
__device__ f16 g_enc[(size_t)TOKC * D];
__device__ f16 g_kb[(size_t)TOK * D];
__device__ f16 g_vb[(size_t)TOK * D];
__device__ f16 g_wqkv[(size_t)3 * D * D];
__device__ f16 g_wo1 [(size_t)D * D];
__device__ f16 g_wq2 [(size_t)D * D];
__device__ f16 g_wkv2[(size_t)2 * D * D];
__device__ f16 g_wo2 [(size_t)D * D];
__device__ f16 g_wff1[(size_t)FFND * D];
__device__ f16 g_wff2[(size_t)D * FFND];

// ---------------- small helpers ----------------
__device__ __forceinline__ float fast_gelu(float x) {
    float u = 0.7978845608028654f * (x + 0.044715f * x * x * x);
    float t = 1.0f - 2.0f / (1.0f + __expf(2.0f * u));
    return 0.5f * x * (1.0f + t);
}

__device__ __forceinline__ uint32_t smem_u32(const void* p) {
    uint32_t a;
    asm("{ .reg .u64 t; cvta.to.shared.u64 t, %1; cvt.u32.u64 %0, t; }" : "=r"(a) : "l"(p));
    return a;
}

#define CP_ASYNC16(dst, src) \
    asm volatile("cp.async.cg.shared.global [%0], [%1], 16;" :: "r"(dst), "l"(src))
#define CP_COMMIT() asm volatile("cp.async.commit_group;" ::: "memory")
#define CP_WAIT1()  asm volatile("cp.async.wait_group 1;" ::: "memory")

__device__ __forceinline__ void ldsm4(uint32_t* r, uint32_t addr) {
    asm volatile("ldmatrix.sync.aligned.m8n8.x4.shared.b16 {%0,%1,%2,%3}, [%4];"
        : "=r"(r[0]), "=r"(r[1]), "=r"(r[2]), "=r"(r[3]) : "r"(addr));
}

__device__ __forceinline__ void mma16816h(float* c, const uint32_t* a, const uint32_t* b) {
    asm volatile("mma.sync.aligned.m16n8k16.row.col.f32.f16.f16.f32 "
        "{%0,%1,%2,%3}, {%4,%5,%6,%7}, {%8,%9}, {%0,%1,%2,%3};"
        : "+f"(c[0]), "+f"(c[1]), "+f"(c[2]), "+f"(c[3])
        : "r"(a[0]), "r"(a[1]), "r"(a[2]), "r"(a[3]), "r"(b[0]), "r"(b[1]));
}

// ---------------- reductions ----------------
__device__ __forceinline__ float blockReduceSum(float v) {
    __shared__ float sh[32];
    int lane = threadIdx.x & 31, wid = threadIdx.x >> 5;
    #pragma unroll
    for (int o = 16; o > 0; o >>= 1) v += __shfl_xor_sync(0xffffffffu, v, o);
    __syncthreads();
    if (lane == 0) sh[wid] = v;
    __syncthreads();
    int nw = blockDim.x >> 5;
    float r = (threadIdx.x < nw) ? sh[threadIdx.x] : 0.0f;
    if (wid == 0) {
        #pragma unroll
        for (int o = 16; o > 0; o >>= 1) r += __shfl_xor_sync(0xffffffffu, r, o);
        if (lane == 0) sh[0] = r;
    }
    __syncthreads();
    return sh[0];
}

__device__ __forceinline__ float blockReduceMax(float v) {
    __shared__ float sh[32];
    int lane = threadIdx.x & 31, wid = threadIdx.x >> 5;
    #pragma unroll
    for (int o = 16; o > 0; o >>= 1) v = fmaxf(v, __shfl_xor_sync(0xffffffffu, v, o));
    __syncthreads();
    if (lane == 0) sh[wid] = v;
    __syncthreads();
    int nw = blockDim.x >> 5;
    float r = (threadIdx.x < nw) ? sh[threadIdx.x] : -3.4e38f;
    if (wid == 0) {
        #pragma unroll
        for (int o = 16; o > 0; o >>= 1) r = fmaxf(r, __shfl_xor_sync(0xffffffffu, r, o));
        if (lane == 0) sh[0] = r;
    }
    __syncthreads();
    return sh[0];
}

// ---------------- elementwise producers (single fp16 out) ----------------
__global__ void __launch_bounds__(256) ln_kernel(
    const float* __restrict__ in, f16* __restrict__ ob,
    const float* __restrict__ gamma, const float* __restrict__ beta,
    const float* __restrict__ sst, const float* __restrict__ temb,
    int iShift, int iScale, int rowsPerB)
{
    long long r = blockIdx.x;
    const float* x = in + r * D;
    float s1 = 0.f, s2 = 0.f;
    for (int d = threadIdx.x; d < D; d += 256) { float v = x[d]; s1 += v; s2 += v * v; }
    s1 = blockReduceSum(s1);
    s2 = blockReduceSum(s2);
    float mean = s1 * (1.0f / D);
    float var  = s2 * (1.0f / D) - mean * mean;
    float rstd = rsqrtf(var + EPSV);
    int b = (int)(r / rowsPerB);
    for (int d = threadIdx.x; d < D; d += 256) {
        float y = (x[d] - mean) * rstd;
        if (sst) {
            float sc = sst[iScale * D + d] + temb[((long long)b * 6 + iScale) * D + d];
            float sh = sst[iShift * D + d] + temb[((long long)b * 6 + iShift) * D + d];
            y = y * (1.f + sc) + sh;
        } else if (gamma) {
            y = y * gamma[d] + beta[d];
        }
        ob[r * D + d] = __float2half_rn(y);
    }
}

__global__ void __launch_bounds__(256) rms_heads_kernel(
    const float* __restrict__ in, int ldin, int off,
    const float* __restrict__ w, f16* __restrict__ ob, int Srows,
    const float* __restrict__ rcos, const float* __restrict__ rsin)
{
    long long r = blockIdx.x;
    int b = (int)(r / Srows), s = (int)(r % Srows);
    const float* x = in + r * ldin + off;
    float s2 = 0.f;
    for (int d = threadIdx.x; d < D; d += 256) { float v = x[d]; s2 += v * v; }
    s2 = blockReduceSum(s2);
    float rms = rsqrtf(s2 * (1.0f / D) + EPSV);
    for (int d = threadIdx.x; d < D; d += 256) {
        int h = d >> 7, dd = d & 127;
        float v = x[d] * rms * w[d];
        if (rcos) {
            int pd = (dd < 64) ? d + 64 : d - 64;
            float vp = x[pd] * rms * w[pd];
            float c = rcos[s * HDIM + dd], sn = rsin[s * HDIM + dd];
            v = (dd < 64) ? (v * c - vp * sn) : (v * c + vp * sn);
        }
        ob[(((long long)(b * NH + h)) * Srows + s) * HDIM + dd] = __float2half_rn(v);
    }
}

__global__ void __launch_bounds__(256) vtrans_kernel(
    const float* __restrict__ in, int ldin, int off,
    f16* __restrict__ ob, int Srows, long long total)
{
    for (long long i = blockIdx.x * 256LL + threadIdx.x; i < total; i += (long long)gridDim.x * 256) {
        long long r = i / D; int col = (int)(i % D);
        int h = col >> 7, d = col & 127;
        int b = (int)(r / Srows), s = (int)(r % Srows);
        ob[(((long long)(b * NH + h)) * HDIM + d) * Srows + s] =
            __float2half_rn(in[r * ldin + off + col]);
    }
}

// softmax: fp32 logits in (register-cached), fp16 probs out
__global__ void __launch_bounds__(256) softmax_kernel(
    const float* __restrict__ p, f16* __restrict__ ob, int len)
{
    long long r = blockIdx.x;
    const float* x = p + r * (long long)len;
    int nper = len >> 8;           // 8 for 2048, 2 for 512
    float xv[8];
    float mx = -3.4e38f;
    for (int i = 0; i < nper; i++) {
        xv[i] = x[threadIdx.x + (i << 8)];
        mx = fmaxf(mx, xv[i]);
    }
    mx = blockReduceMax(mx);
    float sum = 0.f;
    for (int i = 0; i < nper; i++) { xv[i] = __expf(xv[i] - mx); sum += xv[i]; }
    sum = blockReduceSum(sum);
    float inv = 1.0f / sum;
    for (int i = 0; i < nper; i++)
        ob[r * (long long)len + threadIdx.x + (i << 8)] = __float2half_rn(xv[i] * inv);
}

// fp32 -> fp16
__global__ void __launch_bounds__(256) conv_kernel(
    const float* __restrict__ in, f16* __restrict__ ob, long long n)
{
    for (long long i = blockIdx.x * 256LL + threadIdx.x; i < n; i += (long long)gridDim.x * 256)
        ob[i] = __float2half_rn(in[i]);
}

// ---------------- fp16 single-product GEMM ----------------
// C = alpha * A @ B^T (+bias +epilogue); A [M,K] fp16, B [N,K] fp16
// BM=BN=128, BK=32, 3-stage cp.async, 8 warps (64x32 per warp), 2 CTAs/SM
#define STAGE_BYTES 16384
#define OFF_A 0
#define OFF_B 8192
#define NSTAGE 3
#define GEMM_SMEM (NSTAGE * STAGE_BYTES)

__device__ __forceinline__ uint32_t tswz(int row, int chunk) {
    return (uint32_t)(row * 64 + ((chunk ^ (row & 3)) << 4));
}

__global__ void __launch_bounds__(256, 2) gemm_h1_kernel(
    const f16* __restrict__ A, const f16* __restrict__ B,
    float* __restrict__ C, f16* __restrict__ Cf,
    int K, int lda, int ldb, int ldc,
    long long sAo, long long sAi, long long sBo, long long sBi,
    long long sCo, long long sCi, int innerN,
    const float* __restrict__ bias, float alpha, int mode,
    const float* __restrict__ res,
    const float* __restrict__ sst, const float* __restrict__ temb,
    int modIdx)
{
    extern __shared__ char smem[];
    uint32_t sbase = smem_u32(smem);
    int tid = threadIdx.x, wid = tid >> 5, lane = tid & 31;

    int bi = blockIdx.z;
    long long aBase = (long long)(bi / innerN) * sAo + (long long)(bi % innerN) * sAi;
    long long bBase = (long long)(bi / innerN) * sBo + (long long)(bi % innerN) * sBi;
    long long cBase = (long long)(bi / innerN) * sCo + (long long)(bi % innerN) * sCi;
    int m0 = blockIdx.y * 128, n0 = blockIdx.x * 128;

    const f16* Ap = A + aBase + (long long)m0 * lda;
    const f16* Bp = B + bBase + (long long)n0 * ldb;

    int lrow = tid >> 2, lch = tid & 3;
    int NC = K >> 5;

    auto load_stage = [&](int c) {
        int s = c % NSTAGE;
        uint32_t st = sbase + s * STAGE_BYTES;
        int k0 = c << 5;
        #pragma unroll
        for (int half = 0; half < 2; half++) {
            int row = lrow + half * 64;
            uint32_t sw = tswz(row, lch);
            long long gk = k0 + lch * 8;
            CP_ASYNC16(st + OFF_A + sw, Ap + (long long)row * lda + gk);
            CP_ASYNC16(st + OFF_B + sw, Bp + (long long)row * ldb + gk);
        }
    };

    float acc[4][4][4];
    #pragma unroll
    for (int i = 0; i < 4; i++)
        #pragma unroll
        for (int j = 0; j < 4; j++)
            #pragma unroll
            for (int e = 0; e < 4; e++) acc[i][j][e] = 0.f;

    int wm = (wid >> 2) * 64, wn = (wid & 3) * 32;

    load_stage(0); CP_COMMIT();
    if (NC > 1) load_stage(1);
    CP_COMMIT();

    for (int c = 0; c < NC; c++) {
        int s = c % NSTAGE;
        CP_WAIT1();
        __syncthreads();
        if (c + 2 < NC) load_stage(c + 2);
        CP_COMMIT();

        uint32_t st = sbase + s * STAGE_BYTES;
        #pragma unroll
        for (int kk = 0; kk < 2; kk++) {
            uint32_t ah[4][4], bh[4][2];
            int rA = lane & 15, cA = (kk << 1) + (lane >> 4);
            #pragma unroll
            for (int mt = 0; mt < 4; mt++)
                ldsm4(ah[mt], st + OFF_A + tswz(wm + mt * 16 + rA, cA));
            int rB = (lane & 7) + ((lane >> 4) << 3);
            int cB = (kk << 1) + ((lane >> 3) & 1);
            #pragma unroll
            for (int ntp = 0; ntp < 2; ntp++) {
                uint32_t t[4];
                ldsm4(t, st + OFF_B + tswz(wn + ntp * 16 + rB, cB));
                bh[2*ntp][0]=t[0]; bh[2*ntp][1]=t[1]; bh[2*ntp+1][0]=t[2]; bh[2*ntp+1][1]=t[3];
            }
            #pragma unroll
            for (int mt = 0; mt < 4; mt++)
                #pragma unroll
                for (int nt = 0; nt < 4; nt++)
                    mma16816h(acc[mt][nt], ah[mt], bh[nt]);
        }
    }

    // ---- epilogue ----
    int qrow = lane >> 2, qcol = (lane & 3) * 2;
    #pragma unroll
    for (int mt = 0; mt < 4; mt++) {
        #pragma unroll
        for (int nt = 0; nt < 4; nt++) {
            #pragma unroll
            for (int e = 0; e < 4; e++) {
                long long rrow = m0 + wm + mt * 16 + qrow + ((e >> 1) ? 8 : 0);
                int col = n0 + wn + nt * 8 + qcol + (e & 1);
                float v = acc[mt][nt][e] * alpha;
                if (bias) v += bias[col];
                if (mode == 1) v = fast_gelu(v);
                long long ci = cBase + rrow * ldc + col;
                if (mode == 2) {
                    int b_ = (int)(rrow >> 11);  // 2048 rows per batch
                    float g = sst[(long long)modIdx * D + col] +
                              temb[((long long)b_ * 6 + modIdx) * D + col];
                    v = res[ci] + g * v;
                } else if (mode == 3) {
                    v = res[ci] + v;
                }
                if (C)  C[ci]  = v;
                if (Cf) Cf[ci] = __float2half_rn(v);
            }
        }
    }
}

// ---------------- host launch helper ----------------
static void gemm(const f16* A, const f16* B, float* C, f16* Cf,
                 int M, int N, int K, int lda, int ldb, int ldc,
                 long long sAo, long long sAi, long long sBo, long long sBi,
                 long long sCo, long long sCi, int innerN, int nbatch,
                 const float* bias, float alpha, int mode,
                 const float* res, const float* sst, const float* temb,
                 int modIdx)
{
    dim3 grid(N / 128, M / 128, nbatch), block(256);
    gemm_h1_kernel<<<grid, block, GEMM_SMEM>>>(
        A, B, C, Cf, K, lda, ldb, ldc,
        sAo, sAi, sBo, sBi, sCo, sCi, innerN,
        bias, alpha, mode, res, sst, temb, modIdx);
}

#define GETP(sym) ({ void* _p; cudaGetSymbolAddress(&_p, sym); _p; })

extern "C" void kernel_launch(void* const* d_in, const int* in_sizes, int n_in,
                              void* d_out, int out_size)
{
    const float* h    = (const float*)d_in[0];
    const float* enc  = (const float*)d_in[1];
    const float* temb = (const float*)d_in[2];
    const float* rcos = (const float*)d_in[3];
    const float* rsin = (const float*)d_in[4];
    const float* sst  = (const float*)d_in[5];
    const float* w_qkv = (const float*)d_in[6];
    const float* b_qkv = (const float*)d_in[7];
    const float* rms_q1 = (const float*)d_in[8];
    const float* rms_k1 = (const float*)d_in[9];
    const float* w_o1 = (const float*)d_in[10];
    const float* b_o1 = (const float*)d_in[11];
    const float* ln2_g = (const float*)d_in[12];
    const float* ln2_b = (const float*)d_in[13];
    const float* w_q2 = (const float*)d_in[14];
    const float* b_q2 = (const float*)d_in[15];
    const float* w_kv2 = (const float*)d_in[16];
    const float* b_kv2 = (const float*)d_in[17];
    const float* rms_q2 = (const float*)d_in[18];
    const float* rms_k2 = (const float*)d_in[19];
    const float* w_o2 = (const float*)d_in[20];
    const float* b_o2 = (const float*)d_in[21];
    const float* w_ff1 = (const float*)d_in[22];
    const float* b_ff1 = (const float*)d_in[23];
    const float* w_ff2 = (const float*)d_in[24];
    const float* b_ff2 = (const float*)d_in[25];
    float* out = (float*)d_out;

    cudaFuncSetAttribute(gemm_h1_kernel, cudaFuncAttributeMaxDynamicSharedMemorySize, GEMM_SMEM);

    float* pqkv = (float*)GETP(g_qkv);
    float* pkv2 = (float*)GETP(g_kv2);
    float* ph1  = (float*)GETP(g_h1);
    float* ph2  = (float*)GETP(g_h2);
    float* plog = (float*)GETP(g_logits);
    f16 *xb=(f16*)GETP(g_x);
    f16 *qb=(f16*)GETP(g_q);
    f16 *ab=(f16*)GETP(g_a);
    f16 *mb=(f16*)GETP(g_m);
    f16 *Pb=(f16*)GETP(g_P);
    f16 *encb=(f16*)GETP(g_enc);
    f16 *kb=(f16*)GETP(g_kb), *vb=(f16*)GETP(g_vb);
    f16 *wqkv=(f16*)GETP(g_wqkv);
    f16 *wo1=(f16*)GETP(g_wo1);
    f16 *wq2=(f16*)GETP(g_wq2);
    f16 *wkv2=(f16*)GETP(g_wkv2);
    f16 *wo2=(f16*)GETP(g_wo2);
    f16 *wff1=(f16*)GETP(g_wff1);
    f16 *wff2=(f16*)GETP(g_wff2);

    const float scale = 0.08838834764831845f;
    const long long uQ  = (long long)SSELF * HDIM;
    const long long uL  = (long long)SSELF * SSELF;
    const long long uV  = (long long)HDIM * SSELF;
    const long long uK2 = (long long)SCROSS * HDIM;
    const long long uL2 = (long long)SSELF * SCROSS;
    const long long uV2 = (long long)HDIM * SCROSS;

    // 0) ln ; 1) wqkv convert ; 2) qkv GEMM (profiled launch idx 2)
    ln_kernel<<<TOK, 256>>>(h, xb, nullptr, nullptr, sst, temb, 0, 1, SSELF);
    conv_kernel<<<2048, 256>>>(w_qkv, wqkv, (long long)3 * D * D);
    gemm(xb, wqkv, pqkv, nullptr, TOK, 3 * D, D, D, D, 3 * D,
         0,0,0,0,0,0,1,1, b_qkv, 1.f, 0, nullptr, nullptr, nullptr, 0);
    // other weight converts
    conv_kernel<<<1024, 256>>>(w_o1,  wo1,  (long long)D * D);
    conv_kernel<<<1024, 256>>>(w_q2,  wq2,  (long long)D * D);
    conv_kernel<<<1024, 256>>>(w_kv2, wkv2, (long long)2 * D * D);
    conv_kernel<<<1024, 256>>>(w_o2,  wo2,  (long long)D * D);
    conv_kernel<<<2048, 256>>>(w_ff1, wff1, (long long)FFND * D);
    conv_kernel<<<2048, 256>>>(w_ff2, wff2, (long long)D * FFND);
    conv_kernel<<<1024, 256>>>(enc,  encb, (long long)TOKC * D);
    // heads
    rms_heads_kernel<<<TOK, 256>>>(pqkv, 3 * D, 0, rms_q1, qb, SSELF, rcos, rsin);
    rms_heads_kernel<<<TOK, 256>>>(pqkv, 3 * D, D, rms_k1, kb, SSELF, rcos, rsin);
    vtrans_kernel<<<2048, 256>>>(pqkv, 3 * D, 2 * D, vb, SSELF, (long long)TOK * D);
    // logits = scale * q k^T
    gemm(qb, kb, plog, nullptr, SSELF, SSELF, HDIM, HDIM, HDIM, SSELF,
         NH * uQ, uQ, NH * uQ, uQ, NH * uL, uL, NH, BH,
         nullptr, scale, 0, nullptr, nullptr, nullptr, 0);
    softmax_kernel<<<BH * SSELF, 256>>>(plog, Pb, SSELF);
    // attn = P @ V -> fp16 merged [TOK, D]
    gemm(Pb, vb, nullptr, ab, SSELF, HDIM, SSELF, SSELF, SSELF, D,
         NH * uL, uL, NH * uV, uV, (long long)SSELF * D, HDIM, NH, BH,
         nullptr, 1.f, 0, nullptr, nullptr, nullptr, 0);
    // h1 = h + gate_sa * (attn W_o1^T + b)
    gemm(ab, wo1, ph1, nullptr, TOK, D, D, D, D, D,
         0,0,0,0,0,0,1,1, b_o1, 1.f, 2, h, sst, temb, 2);
    // x2 = LN(h1)
    ln_kernel<<<TOK, 256>>>(ph1, xb, ln2_g, ln2_b, nullptr, nullptr, 0, 0, SSELF);
    // q2lin
    gemm(xb, wq2, pqkv, nullptr, TOK, D, D, D, D, D,
         0,0,0,0,0,0,1,1, b_q2, 1.f, 0, nullptr, nullptr, nullptr, 0);
    rms_heads_kernel<<<TOK, 256>>>(pqkv, D, 0, rms_q2, qb, SSELF, nullptr, nullptr);
    // kv2 = enc @ w_kv2^T + b
    gemm(encb, wkv2, pkv2, nullptr, TOKC, 2 * D, D, D, D, 2 * D,
         0,0,0,0,0,0,1,1, b_kv2, 1.f, 0, nullptr, nullptr, nullptr, 0);
    rms_heads_kernel<<<TOKC, 256>>>(pkv2, 2 * D, 0, rms_k2, kb, SCROSS, nullptr, nullptr);
    vtrans_kernel<<<512, 256>>>(pkv2, 2 * D, D, vb, SCROSS, (long long)TOKC * D);
    // logits2
    gemm(qb, kb, plog, nullptr, SSELF, SCROSS, HDIM, HDIM, HDIM, SCROSS,
         NH * uQ, uQ, NH * uK2, uK2, NH * uL2, uL2, NH, BH,
         nullptr, scale, 0, nullptr, nullptr, nullptr, 0);
    softmax_kernel<<<BH * SSELF, 256>>>(plog, Pb, SCROSS);
    // attn2
    gemm(Pb, vb, nullptr, ab, SSELF, HDIM, SCROSS, SCROSS, SCROSS, D,
         NH * uL2, uL2, NH * uV2, uV2, (long long)SSELF * D, HDIM, NH, BH,
         nullptr, 1.f, 0, nullptr, nullptr, nullptr, 0);
    // h2 = h1 + attn2 W_o2^T + b
    gemm(ab, wo2, ph2, nullptr, TOK, D, D, D, D, D,
         0,0,0,0,0,0,1,1, b_o2, 1.f, 3, ph1, nullptr, nullptr, 0);
    // xff
    ln_kernel<<<TOK, 256>>>(ph2, xb, nullptr, nullptr, sst, temb, 3, 4, SSELF);
    // mid = gelu(xff W_ff1^T + b) -> fp16
    gemm(xb, wff1, nullptr, mb, TOK, FFND, D, D, D, FFND,
         0,0,0,0,0,0,1,1, b_ff1, 1.f, 1, nullptr, nullptr, nullptr, 0);
    // out = h2 + gate_ff * (mid W_ff2^T + b)
    gemm(mb, wff2, out, nullptr, TOK, D, FFND, FFND, FFND, D,
         0,0,0,0,0,0,1,1, b_ff2, 1.f, 2, ph2, sst, temb, 5);

    (void)in_sizes; (void)n_in; (void)out_size;
}